// round 15
// baseline (speedup 1.0000x reference)
#include <cuda_runtime.h>
#include <cstdint>

// Problem constants
#define BATCH 32
#define SEQ   4096
#define NDIM  1024
#define MROWS (BATCH * SEQ)          // 131072

// Output layout: [context (B*N)] [attn (B*S)] [coverage_out (B*S)]
#define CTX_OFF 0
#define ATT_OFF (BATCH * NDIM)                       // 32768
#define COV_OFF (BATCH * NDIM + BATCH * SEQ)         // 163840

// Scratch (static device memory; no allocation).
__device__ float g_e8[8 * MROWS];     // per-bc logit partials (BSS-zero trick)
__device__ float g_db[BATCH * NDIM];  // dec_feats + bs + bh
__device__ unsigned g_tile_ctr;       // GEMM tile queue head
__device__ unsigned g_ctx_ctr;        // context chunk queue head
__device__ unsigned g_bar0, g_bar1;   // grid-barrier counters
__device__ unsigned g_bflag[BATCH];   // softmax-done flag per batch

// ---------------------------------------------------------------------------
// helpers
// ---------------------------------------------------------------------------
__device__ __forceinline__ float tanh_fast(float x) {
    float r;
    asm("tanh.approx.f32 %0, %1;" : "=f"(r) : "f"(x));
    return r;
}
__device__ __forceinline__ uint32_t smem_u32(const void* p) {
    uint32_t a;
    asm("{ .reg .u64 t; cvta.to.shared.u64 t, %1; cvt.u32.u64 %0, t; }"
        : "=r"(a) : "l"(p));
    return a;
}
__device__ __forceinline__ void mma_tf32(float* d, const unsigned* a, const unsigned* b) {
    asm volatile(
        "mma.sync.aligned.m16n8k8.row.col.f32.tf32.tf32.f32 "
        "{%0,%1,%2,%3},{%4,%5,%6,%7},{%8,%9},{%0,%1,%2,%3};"
        : "+f"(d[0]), "+f"(d[1]), "+f"(d[2]), "+f"(d[3])
        : "r"(a[0]), "r"(a[1]), "r"(a[2]), "r"(a[3]), "r"(b[0]), "r"(b[1]));
}
#define LDSM_X4(r0, r1, r2, r3, addr) \
    asm volatile("ldmatrix.sync.aligned.m8n8.x4.shared.b16 {%0,%1,%2,%3}, [%4];" \
                 : "=r"(r0), "=r"(r1), "=r"(r2), "=r"(r3) : "r"(addr))
#define CPA16(s, g) \
    asm volatile("cp.async.cg.shared.global [%0], [%1], 16;" :: "r"(s), "l"(g))
#define CPA_COMMIT() asm volatile("cp.async.commit_group;" ::: "memory")

// GEMM tiling
#define BM 128
#define BN 128
#define BK 32
#define NKT (NDIM / BK)   // 32
#define NBUF 3
#define LDK (BK + 4)      // 36 floats per row
#define TILE_A_F (BM * LDK)             // 4608 floats
#define TILE_B_F (BN * LDK)             // 4608 floats
#define STAGE_F (TILE_A_F + TILE_B_F)   // 9216 floats
#define STAGE_BYTES (STAGE_F * 4)       // 36864 B
#define SMEM_FLOATS (NBUF * STAGE_F + 264)
#define SMEM_BYTES (SMEM_FLOATS * 4)
#define NTILES (8 * 1024)               // bc (8) fastest, br (1024)
#define NCTX   (BATCH * (SEQ / 64))     // 2048 context chunks
#define GEMM_CTAS 296                   // 2 per SM x 148 SMs

// ---------------------------------------------------------------------------
// 0) reset counters/flags (runs inside the graph each replay)
// ---------------------------------------------------------------------------
__global__ void init_sync_kernel() {
    int t = threadIdx.x;
    if (t == 0) { g_tile_ctr = 0u; g_ctx_ctr = 0u; g_bar0 = 0u; g_bar1 = 0u; }
    if (t < BATCH) g_bflag[t] = 0u;
}

// all-resident grid barrier (296 CTAs, 2/SM exact -> deadlock-free)
__device__ __forceinline__ void grid_bar(unsigned* ctr) {
    __syncthreads();
    if (threadIdx.x == 0) {
        __threadfence();
        atomicAdd(ctr, 1u);
        while (atomicAdd(ctr, 0u) < GEMM_CTAS) {}
    }
    __syncthreads();
    __threadfence();
}

// ---------------------------------------------------------------------------
// Mega-kernel: dec_feats -> barrier -> GEMM queue -> barrier -> softmax
//              (CTAs 0..31, per-batch flags) -> context queue (flag-gated)
// ---------------------------------------------------------------------------
__global__ __launch_bounds__(256, 2)
void attn_mega_kernel(const float* __restrict__ dec,   // [B,N]
                      const float* __restrict__ A,     // enc_states [M,K]
                      const int*   __restrict__ lens,  // [B]
                      const float* __restrict__ cov,   // [M]
                      const float* __restrict__ Wh,    // [N,K]
                      const float* __restrict__ bh,
                      const float* __restrict__ Ws,
                      const float* __restrict__ bs,
                      const float* __restrict__ wc,
                      const float* __restrict__ v,
                      float* __restrict__ out) {
    extern __shared__ float smem[];
    float* s_e = smem + NBUF * STAGE_F;            // [128]
    unsigned* s_idx = (unsigned*)(s_e + 128);      // [1]
    float* s_red = s_e;                            // softmax reuse (256 would
                                                   // overlap s_idx; use 128+)
    const uint32_t sb = smem_u32(smem);

    const int t = threadIdx.x;
    const int lane = t & 31, wid = t >> 5;
    const int warp_m = wid >> 2, warp_n = wid & 3;   // 2 x 4
    const int g = lane >> 2, tig = lane & 3;

    // ================= Phase A: dec_feats ==================================
    {
        const float4* dv4base = (const float4*)dec;
        for (unsigned task = blockIdx.x; task < BATCH * 32; task += GEMM_CTAS) {
            int b = task >> 5, chunk = task & 31;
            const float4* dv4 = dv4base + b * (NDIM / 4);
#pragma unroll
            for (int j = 0; j < 4; j++) {
                int m = chunk * 32 + wid * 4 + j;
                const float4* wr4 = (const float4*)(Ws + (size_t)m * NDIM);
                float s = 0.0f;
#pragma unroll
                for (int k = lane; k < NDIM / 4; k += 32) {
                    float4 wv = wr4[k], dvv = dv4[k];
                    s += wv.x * dvv.x + wv.y * dvv.y + wv.z * dvv.z + wv.w * dvv.w;
                }
#pragma unroll
                for (int o = 16; o > 0; o >>= 1)
                    s += __shfl_xor_sync(0xffffffffu, s, o);
                if (lane == 0) g_db[b * NDIM + m] = s + bs[m] + bh[m];
            }
        }
    }
    grid_bar(&g_bar0);

    // ================= Phase B: GEMM tile queue ============================
    uint32_t a_off[4];
#pragma unroll
    for (int mt = 0; mt < 4; mt++) {
        int row = warp_m * 64 + mt * 16 + (lane & 15);
        int kc  = (lane >> 4) * 4;
        a_off[mt] = (uint32_t)(row * LDK + kc) * 4;
    }
    uint32_t b_off[2];
#pragma unroll
    for (int p = 0; p < 2; p++) {
        int nrow = warp_n * 32 + p * 16 + (lane & 7) + ((lane >> 4) & 1) * 8;
        int kc   = ((lane >> 3) & 1) * 4;
        b_off[p] = (uint32_t)(TILE_A_F * 4) + (uint32_t)(nrow * LDK + kc) * 4;
    }

#define LOAD_A_HALF(p, bufbase)                                                \
    do {                                                                       \
        const uint32_t _ab = (bufbase);                                        \
        const int _k0 = (p) * BK;                                              \
        _Pragma("unroll")                                                      \
        for (int _i = 0; _i < 4; _i++) {                                       \
            int _c = t + _i * 256;                                             \
            int _r = _c >> 3, _ch = _c & 7;                                    \
            CPA16(_ab + (uint32_t)(_r * LDK + _ch * 4) * 4,                    \
                  Ablk + (size_t)_r * NDIM + _k0 + _ch * 4);                   \
        }                                                                      \
    } while (0)

#define LOAD_B_HALF(p, bufbase)                                                \
    do {                                                                       \
        const uint32_t _bb = (bufbase) + TILE_A_F * 4;                         \
        const int _k0 = (p) * BK;                                              \
        _Pragma("unroll")                                                      \
        for (int _i = 0; _i < 4; _i++) {                                       \
            int _c = t + _i * 256;                                             \
            int _r = _c >> 3, _ch = _c & 7;                                    \
            CPA16(_bb + (uint32_t)(_r * LDK + _ch * 4) * 4,                    \
                  Bblk + (size_t)_r * NDIM + _k0 + _ch * 4);                   \
        }                                                                      \
    } while (0)

#define DO_KK(kk_ofs)                                                          \
    do {                                                                       \
        unsigned af[4][4], bf[4][2];                                           \
        _Pragma("unroll")                                                      \
        for (int mt = 0; mt < 4; mt++)                                         \
            LDSM_X4(af[mt][0], af[mt][1], af[mt][2], af[mt][3],                \
                    (kk_ofs) + a_off[mt]);                                     \
        _Pragma("unroll")                                                      \
        for (int p = 0; p < 2; p++)                                            \
            LDSM_X4(bf[2 * p][0], bf[2 * p][1], bf[2 * p + 1][0],              \
                    bf[2 * p + 1][1], (kk_ofs) + b_off[p]);                    \
        _Pragma("unroll")                                                      \
        for (int mt = 0; mt < 4; mt++)                                         \
            _Pragma("unroll")                                                  \
            for (int nt = 0; nt < 4; nt++)                                     \
                mma_tf32(acc[mt][nt], af[mt], bf[nt]);                         \
    } while (0)

    for (;;) {
        __syncthreads();
        if (t == 0) s_idx[0] = atomicAdd(&g_tile_ctr, 1u);
        __syncthreads();
        const unsigned idx = s_idx[0];
        if (idx >= NTILES) break;

        const int bc = idx & 7;
        const int br = idx >> 3;
        const int b  = br >> 5;
        if ((br & 31) * BM >= lens[b]) continue;   // masked tile -> attn == 0

        const float* Ablk = A  + (size_t)br * BM * NDIM;
        const float* Bblk = Wh + (size_t)bc * BN * NDIM;

        if (t < BM) s_e[t] = 0.0f;

        float acc[4][4][4];
#pragma unroll
        for (int i = 0; i < 4; i++)
#pragma unroll
            for (int j = 0; j < 4; j++)
#pragma unroll
                for (int k = 0; k < 4; k++) acc[i][j][k] = 0.0f;

        LOAD_A_HALF(0, sb); LOAD_B_HALF(0, sb); CPA_COMMIT();
        LOAD_A_HALF(1, sb + STAGE_BYTES); LOAD_B_HALF(1, sb + STAGE_BYTES);
        CPA_COMMIT();

        const uint32_t wrap = sb + NBUF * STAGE_BYTES;
        uint32_t cur = sb;
        uint32_t pf  = sb + 2 * STAGE_BYTES;

        for (int s = 0; s < NKT; ++s) {
            if (s + 1 < NKT) {
                asm volatile("cp.async.wait_group 1;" ::: "memory");
            } else {
                asm volatile("cp.async.wait_group 0;" ::: "memory");
            }
            __syncthreads();

            DO_KK(cur);
            if (s + 2 < NKT) LOAD_A_HALF(s + 2, pf);
            DO_KK(cur + 32);
            if (s + 2 < NKT) { LOAD_B_HALF(s + 2, pf); CPA_COMMIT(); }
            DO_KK(cur + 64);
            DO_KK(cur + 96);

            cur += STAGE_BYTES; if (cur == wrap) cur = sb;
            pf  += STAGE_BYTES; if (pf  == wrap) pf  = sb;
        }

        // fused epilogue: tanh + dot with v
        float vv[4][2], ww[4][2], dd[4][2];
#pragma unroll
        for (int nt = 0; nt < 4; nt++)
#pragma unroll
            for (int j = 0; j < 2; j++) {
                int col = bc * BN + warp_n * 32 + nt * 8 + 2 * tig + j;
                vv[nt][j] = v[col];
                ww[nt][j] = wc[col];
                dd[nt][j] = g_db[b * NDIM + col];
            }

#pragma unroll
        for (int mt = 0; mt < 4; mt++) {
#pragma unroll
            for (int h = 0; h < 2; h++) {
                int rl = warp_m * 64 + mt * 16 + g + 8 * h;
                size_t rg = (size_t)br * BM + rl;
                float cv = cov[rg];
                float sum = 0.0f;
#pragma unroll
                for (int nt = 0; nt < 4; nt++)
#pragma unroll
                    for (int j = 0; j < 2; j++) {
                        float x = acc[mt][nt][2 * h + j] + dd[nt][j] +
                                  cv * ww[nt][j];
                        sum += vv[nt][j] * tanh_fast(x);
                    }
                sum += __shfl_xor_sync(0xffffffffu, sum, 1);
                sum += __shfl_xor_sync(0xffffffffu, sum, 2);
                if (tig == 0) atomicAdd(&s_e[rl], sum);
            }
        }
        __syncthreads();
        if (t < BM) g_e8[(size_t)bc * MROWS + (size_t)br * BM + t] = s_e[t];
    }
#undef LOAD_A_HALF
#undef LOAD_B_HALF
#undef DO_KK

    grid_bar(&g_bar1);

    // ================= Phase C: softmax (CTAs 0..31) =======================
    if (blockIdx.x < BATCH) {
        const int b = blockIdx.x;
        const int len = lens[b];

        // zero the context region (accumulated by atomics in phase D)
#pragma unroll
        for (int i = 0; i < NDIM / 256; i++)
            out[CTX_OFF + b * NDIM + i * 256 + t] = 0.0f;

        float ev[16];
        float lmax = -1e30f;
#pragma unroll
        for (int i = 0; i < 16; i++) {
            int s = t + i * 256;
            size_t idx = (size_t)b * SEQ + s;
            float e = 0.0f;
#pragma unroll
            for (int p = 0; p < 8; p++) e += g_e8[(size_t)p * MROWS + idx];
            ev[i] = e;
            if (s < len) lmax = fmaxf(lmax, e);
        }
        // warp reduce then smem (s_red has 128+ slots; use 8 warp results)
        for (int o = 16; o > 0; o >>= 1)
            lmax = fmaxf(lmax, __shfl_xor_sync(0xffffffffu, lmax, o));
        if (lane == 0) s_red[wid] = lmax;
        __syncthreads();
        float m = fmaxf(fmaxf(fmaxf(s_red[0], s_red[1]), fmaxf(s_red[2], s_red[3])),
                        fmaxf(fmaxf(s_red[4], s_red[5]), fmaxf(s_red[6], s_red[7])));
        __syncthreads();

        float lsum = 0.0f;
#pragma unroll
        for (int i = 0; i < 16; i++) {
            int s = t + i * 256;
            float x = (s < len) ? __expf(ev[i] - m) : 0.0f;
            ev[i] = x;
            lsum += x;
        }
        for (int o = 16; o > 0; o >>= 1)
            lsum += __shfl_xor_sync(0xffffffffu, lsum, o);
        if (lane == 0) s_red[wid] = lsum;
        __syncthreads();
        float inv = 1.0f / (s_red[0] + s_red[1] + s_red[2] + s_red[3] +
                            s_red[4] + s_red[5] + s_red[6] + s_red[7]);

#pragma unroll
        for (int i = 0; i < 16; i++) {
            int s = t + i * 256;
            float a = ev[i] * inv;
            out[ATT_OFF + b * SEQ + s] = a;
            out[COV_OFF + b * SEQ + s] = cov[b * SEQ + s] + a;
        }
        __syncthreads();
        __threadfence();
        if (t == 0) atomicExch(&g_bflag[b], 1u);
    }

    // ================= Phase D: context (flag-gated queue) =================
    {
        float* sa = s_e;                        // [64] reuse
        const float* out_attn = out + ATT_OFF;
        float* ctx = out + CTX_OFF;
        for (;;) {
            __syncthreads();
            if (t == 0) s_idx[0] = atomicAdd(&g_ctx_ctr, 1u);
            __syncthreads();
            const unsigned idx = s_idx[0];
            if (idx >= NCTX) break;
            const int b = idx >> 6;
            const int sc = idx & 63;
            if ((sc * 64) >= lens[b]) continue;  // fully masked chunk
            if (t == 0)
                while (atomicAdd(&g_bflag[b], 0u) == 0u) {}
            __syncthreads();
            __threadfence();

            if (t < 64) sa[t] = out_attn[b * SEQ + sc * 64 + t];
            int any = __syncthreads_or((t < 64) ? (sa[t] != 0.0f) : 0);
            if (!any) continue;

            const float4* base =
                (const float4*)(A + ((size_t)b * SEQ + sc * 64) * NDIM);
            float4 acc4 = make_float4(0.f, 0.f, 0.f, 0.f);
#pragma unroll 4
            for (int s = 0; s < 64; s++) {
                float a = sa[s];
                float4 x = base[s * 256 + t];
                acc4.x += a * x.x;
                acc4.y += a * x.y;
                acc4.z += a * x.z;
                acc4.w += a * x.w;
            }
            float* c = ctx + b * NDIM + t * 4;
            atomicAdd(c + 0, acc4.x);
            atomicAdd(c + 1, acc4.y);
            atomicAdd(c + 2, acc4.z);
            atomicAdd(c + 3, acc4.w);
        }
    }
}

// ---------------------------------------------------------------------------
// launch
// ---------------------------------------------------------------------------
extern "C" void kernel_launch(void* const* d_in, const int* in_sizes, int n_in,
                              void* d_out, int out_size) {
    const float* dec  = (const float*)d_in[0];  // [B,N]
    const float* enc  = (const float*)d_in[1];  // [B,S,N]
    const int*   lens = (const int*)  d_in[2];  // [B]
    const float* cov  = (const float*)d_in[3];  // [B,S]
    const float* Wh   = (const float*)d_in[4];  // [N,N]
    const float* bh   = (const float*)d_in[5];  // [N]
    const float* Ws   = (const float*)d_in[6];  // [N,N]
    const float* bs   = (const float*)d_in[7];  // [N]
    const float* wc   = (const float*)d_in[8];  // [N]
    const float* v    = (const float*)d_in[9];  // [N]
    float* out = (float*)d_out;

    cudaFuncSetAttribute(attn_mega_kernel,
                         cudaFuncAttributeMaxDynamicSharedMemorySize, SMEM_BYTES);

    init_sync_kernel<<<1, 64>>>();
    attn_mega_kernel<<<GEMM_CTAS, 256, SMEM_BYTES>>>(dec, enc, lens, cov, Wh, bh,
                                                     Ws, bs, wc, v, out);
}

// round 16
// speedup vs baseline: 1.0671x; 1.0671x over previous
#include <cuda_runtime.h>
#include <cstdint>

// Problem constants
#define BATCH 32
#define SEQ   4096
#define NDIM  1024
#define MROWS (BATCH * SEQ)          // 131072

// Output layout: [context (B*N)] [attn (B*S)] [coverage_out (B*S)]
#define CTX_OFF 0
#define ATT_OFF (BATCH * NDIM)                       // 32768
#define COV_OFF (BATCH * NDIM + BATCH * SEQ)         // 163840

// Scratch (static device memory; no allocation).
// g_e8: per-bc logit partials, plain stores. Masked rows never written,
// stay 0 (BSS) — softmax only reads s < len.
__device__ float g_e8[8 * MROWS];
__device__ float g_db[BATCH * NDIM];  // dec_feats + bs + bh
__device__ unsigned g_tile_ctr;       // valid-tile queue head
__device__ int g_prefix[33];          // prefix of per-batch valid row-blocks
__device__ unsigned g_total;          // total valid row-blocks

// ---------------------------------------------------------------------------
// helpers
// ---------------------------------------------------------------------------
__device__ __forceinline__ float tanh_fast(float x) {
    float r;
    asm("tanh.approx.f32 %0, %1;" : "=f"(r) : "f"(x));
    return r;
}
__device__ __forceinline__ uint32_t smem_u32(const void* p) {
    uint32_t a;
    asm("{ .reg .u64 t; cvta.to.shared.u64 t, %1; cvt.u32.u64 %0, t; }"
        : "=r"(a) : "l"(p));
    return a;
}
__device__ __forceinline__ void mma_tf32(float* d, const unsigned* a, const unsigned* b) {
    asm volatile(
        "mma.sync.aligned.m16n8k8.row.col.f32.tf32.tf32.f32 "
        "{%0,%1,%2,%3},{%4,%5,%6,%7},{%8,%9},{%0,%1,%2,%3};"
        : "+f"(d[0]), "+f"(d[1]), "+f"(d[2]), "+f"(d[3])
        : "r"(a[0]), "r"(a[1]), "r"(a[2]), "r"(a[3]), "r"(b[0]), "r"(b[1]));
}
#define LDSM_X4(r0, r1, r2, r3, addr) \
    asm volatile("ldmatrix.sync.aligned.m8n8.x4.shared.b16 {%0,%1,%2,%3}, [%4];" \
                 : "=r"(r0), "=r"(r1), "=r"(r2), "=r"(r3) : "r"(addr))
#define CPA16(s, g) \
    asm volatile("cp.async.cg.shared.global [%0], [%1], 16;" :: "r"(s), "l"(g))
#define CPA_COMMIT() asm volatile("cp.async.commit_group;" ::: "memory")

// ---------------------------------------------------------------------------
// 1) dec_feats + (block 0,0) valid-tile prefix table + counter reset
// ---------------------------------------------------------------------------
__global__ void dec_feats_kernel(const float* __restrict__ dec,
                                 const float* __restrict__ Ws,
                                 const float* __restrict__ bs,
                                 const float* __restrict__ bh,
                                 const int* __restrict__ lens) {
    if (blockIdx.x == 0 && blockIdx.y == 0) {
        __shared__ int nb[32];
        int t0 = threadIdx.x;
        if (t0 < 32) nb[t0] = (lens[t0] + 127) >> 7;   // row-blocks of 128
        __syncthreads();
        if (t0 < 33) {
            int p = 0;
            for (int i = 0; i < t0; i++) p += nb[i];
            g_prefix[t0] = p;
            if (t0 == 32) g_total = (unsigned)p;
        }
        if (t0 == 0) g_tile_ctr = 0u;
    }
    int b = blockIdx.x;
    int chunk = blockIdx.y;
    int w = threadIdx.x >> 5;
    int lane = threadIdx.x & 31;
    const float4* dv4 = (const float4*)(dec + b * NDIM);
#pragma unroll
    for (int j = 0; j < 4; j++) {
        int m = chunk * 32 + w * 4 + j;
        const float4* wr4 = (const float4*)(Ws + (size_t)m * NDIM);
        float s = 0.0f;
#pragma unroll
        for (int k = lane; k < NDIM / 4; k += 32) {
            float4 wv = wr4[k], dvv = dv4[k];
            s += wv.x * dvv.x + wv.y * dvv.y + wv.z * dvv.z + wv.w * dvv.w;
        }
#pragma unroll
        for (int o = 16; o > 0; o >>= 1) s += __shfl_xor_sync(0xffffffffu, s, o);
        if (lane == 0) g_db[b * NDIM + m] = s + bs[m] + bh[m];
    }
}

// ---------------------------------------------------------------------------
// 2) PERSISTENT fused GEMM — valid-only tile queue with index prefetch.
//    Tiles: BM=128, BN=128, BK=32. 296 CTAs (2/SM), 256 thr, warp tile 64x32.
// ---------------------------------------------------------------------------
#define BM 128
#define BN 128
#define BK 32
#define NKT (NDIM / BK)   // 32
#define NBUF 3
#define LDK (BK + 4)      // 36 floats per row
#define TILE_A_F (BM * LDK)             // 4608 floats
#define TILE_B_F (BN * LDK)             // 4608 floats
#define STAGE_F (TILE_A_F + TILE_B_F)   // 9216 floats
#define STAGE_BYTES (STAGE_F * 4)       // 36864 B
#define SMEM_FLOATS (NBUF * STAGE_F + 168)
#define SMEM_BYTES (SMEM_FLOATS * 4)    // 111264 B  (2 CTAs/SM: 222528 B)
#define GEMM_CTAS 296                   // 2 per SM x 148 SMs

__global__ __launch_bounds__(256, 2)
void attn_gemm_kernel(const float* __restrict__ A,    // enc_states [M,K]
                      const float* __restrict__ Wh,   // [N,K]
                      const float* __restrict__ cov,  // [M]
                      const float* __restrict__ wc,   // [N]
                      const float* __restrict__ v,    // [N]
                      const int*   __restrict__ lens) {
    extern __shared__ float smem[];
    float* s_e = smem + NBUF * STAGE_F;            // [128]
    unsigned* s_idx = (unsigned*)(s_e + 128);      // [1]
    int* s_pre = (int*)(s_e + 132);                // [33]
    const uint32_t sb = smem_u32(smem);

    const int t = threadIdx.x;
    const int lane = t & 31, wid = t >> 5;
    const int warp_m = wid >> 2, warp_n = wid & 3;   // 2 x 4
    const int g = lane >> 2, tig = lane & 3;

    // prefix table -> smem; initial queue fetch
    if (t < 33) s_pre[t] = g_prefix[t];
    if (t == 0) s_idx[0] = atomicAdd(&g_tile_ctr, 1u);
    const unsigned ntv = 8u * g_total;             // 8 bc per valid row-block
    __syncthreads();

    // ldmatrix per-thread byte offsets (within a stage), kk=0.
    uint32_t a_off[4];
#pragma unroll
    for (int mt = 0; mt < 4; mt++) {
        int row = warp_m * 64 + mt * 16 + (lane & 15);
        int kc  = (lane >> 4) * 4;
        a_off[mt] = (uint32_t)(row * LDK + kc) * 4;
    }
    uint32_t b_off[2];
#pragma unroll
    for (int p = 0; p < 2; p++) {
        int nrow = warp_n * 32 + p * 16 + (lane & 7) + ((lane >> 4) & 1) * 8;
        int kc   = ((lane >> 3) & 1) * 4;
        b_off[p] = (uint32_t)(TILE_A_F * 4) + (uint32_t)(nrow * LDK + kc) * 4;
    }

#define LOAD_A_HALF(p, bufbase)                                                \
    do {                                                                       \
        const uint32_t _ab = (bufbase);                                        \
        const int _k0 = (p) * BK;                                              \
        _Pragma("unroll")                                                      \
        for (int _i = 0; _i < 4; _i++) {                                       \
            int _c = t + _i * 256;                                             \
            int _r = _c >> 3, _ch = _c & 7;                                    \
            CPA16(_ab + (uint32_t)(_r * LDK + _ch * 4) * 4,                    \
                  Ablk + (size_t)_r * NDIM + _k0 + _ch * 4);                   \
        }                                                                      \
    } while (0)

#define LOAD_B_HALF(p, bufbase)                                                \
    do {                                                                       \
        const uint32_t _bb = (bufbase) + TILE_A_F * 4;                         \
        const int _k0 = (p) * BK;                                              \
        _Pragma("unroll")                                                      \
        for (int _i = 0; _i < 4; _i++) {                                       \
            int _c = t + _i * 256;                                             \
            int _r = _c >> 3, _ch = _c & 7;                                    \
            CPA16(_bb + (uint32_t)(_r * LDK + _ch * 4) * 4,                    \
                  Bblk + (size_t)_r * NDIM + _k0 + _ch * 4);                   \
        }                                                                      \
    } while (0)

#define DO_KK(kk_ofs)                                                          \
    do {                                                                       \
        unsigned af[4][4], bf[4][2];                                           \
        _Pragma("unroll")                                                      \
        for (int mt = 0; mt < 4; mt++)                                         \
            LDSM_X4(af[mt][0], af[mt][1], af[mt][2], af[mt][3],                \
                    (kk_ofs) + a_off[mt]);                                     \
        _Pragma("unroll")                                                      \
        for (int p = 0; p < 2; p++)                                            \
            LDSM_X4(bf[2 * p][0], bf[2 * p][1], bf[2 * p + 1][0],              \
                    bf[2 * p + 1][1], (kk_ofs) + b_off[p]);                    \
        _Pragma("unroll")                                                      \
        for (int mt = 0; mt < 4; mt++)                                         \
            _Pragma("unroll")                                                  \
            for (int nt = 0; nt < 4; nt++)                                     \
                mma_tf32(acc[mt][nt], af[mt], bf[nt]);                         \
    } while (0)

    for (;;) {
        const unsigned idx = s_idx[0];
        if (idx >= ntv) return;

        // decode: bc fastest; vt -> (b, br) via warp ballot on prefix table
        const int bc = idx & 7;
        const int vt = (int)(idx >> 3);
        int cond = (vt >= s_pre[lane]) && (vt < s_pre[lane + 1]);
        unsigned mask = __ballot_sync(0xffffffffu, cond);
        const int b = __ffs(mask) - 1;
        const int br = b * 32 + (vt - s_pre[b]);

        const float* Ablk = A  + (size_t)br * BM * NDIM;
        const float* Bblk = Wh + (size_t)bc * BN * NDIM;

        if (t < BM) s_e[t] = 0.0f;

        float acc[4][4][4];
#pragma unroll
        for (int i = 0; i < 4; i++)
#pragma unroll
            for (int j = 0; j < 4; j++)
#pragma unroll
                for (int k = 0; k < 4; k++) acc[i][j][k] = 0.0f;

        LOAD_A_HALF(0, sb); LOAD_B_HALF(0, sb); CPA_COMMIT();
        LOAD_A_HALF(1, sb + STAGE_BYTES); LOAD_B_HALF(1, sb + STAGE_BYTES);
        CPA_COMMIT();

        const uint32_t wrap = sb + NBUF * STAGE_BYTES;
        uint32_t cur = sb;
        uint32_t pf  = sb + 2 * STAGE_BYTES;

        for (int s = 0; s < NKT; ++s) {
            if (s + 1 < NKT) {
                asm volatile("cp.async.wait_group 1;" ::: "memory");
            } else {
                asm volatile("cp.async.wait_group 0;" ::: "memory");
            }
            __syncthreads();

            DO_KK(cur);
            if (s + 2 < NKT) LOAD_A_HALF(s + 2, pf);
            DO_KK(cur + 32);
            if (s + 2 < NKT) { LOAD_B_HALF(s + 2, pf); CPA_COMMIT(); }
            DO_KK(cur + 64);
            // prefetch NEXT tile index under tensor work; published by the
            // next stage's __syncthreads (and the epilogue barrier).
            if (s == 16 && t == 0) s_idx[0] = atomicAdd(&g_tile_ctr, 1u);
            DO_KK(cur + 96);

            cur += STAGE_BYTES; if (cur == wrap) cur = sb;
            pf  += STAGE_BYTES; if (pf  == wrap) pf  = sb;
        }

        // ---- fused epilogue: tanh + dot with v, reduce over columns ----
        float vv[4][2], ww[4][2], dd[4][2];
#pragma unroll
        for (int nt = 0; nt < 4; nt++)
#pragma unroll
            for (int j = 0; j < 2; j++) {
                int col = bc * BN + warp_n * 32 + nt * 8 + 2 * tig + j;
                vv[nt][j] = v[col];
                ww[nt][j] = wc[col];
                dd[nt][j] = g_db[b * NDIM + col];
            }

#pragma unroll
        for (int mt = 0; mt < 4; mt++) {
#pragma unroll
            for (int h = 0; h < 2; h++) {
                int rl = warp_m * 64 + mt * 16 + g + 8 * h;
                size_t rg = (size_t)br * BM + rl;
                float cv = cov[rg];
                float sum = 0.0f;
#pragma unroll
                for (int nt = 0; nt < 4; nt++)
#pragma unroll
                    for (int j = 0; j < 2; j++) {
                        float x = acc[mt][nt][2 * h + j] + dd[nt][j] +
                                  cv * ww[nt][j];
                        sum += vv[nt][j] * tanh_fast(x);
                    }
                sum += __shfl_xor_sync(0xffffffffu, sum, 1);
                sum += __shfl_xor_sync(0xffffffffu, sum, 2);
                if (tig == 0) atomicAdd(&s_e[rl], sum);
            }
        }
        __syncthreads();
        // private slice per bc -> plain store (no global atomics, no pre-zero)
        if (t < BM) g_e8[(size_t)bc * MROWS + (size_t)br * BM + t] = s_e[t];
        __syncthreads();   // protect s_e/s_idx reuse for the next iteration
    }
#undef LOAD_A_HALF
#undef LOAD_B_HALF
#undef DO_KK
}

// ---------------------------------------------------------------------------
// 3) masked renormalized softmax per batch row + coverage_out (+ ctx zeroing)
// ---------------------------------------------------------------------------
__global__ void softmax_kernel(const float* __restrict__ cov,
                               const int* __restrict__ lens,
                               float* __restrict__ out) {
    const int b = blockIdx.x;
    const int t = threadIdx.x;  // 256
    __shared__ float red[256];
    const int len = lens[b];

    // zero the context region (accumulated by atomics in context_kernel)
#pragma unroll
    for (int i = 0; i < NDIM / 256; i++)
        out[CTX_OFF + b * NDIM + i * 256 + t] = 0.0f;

    float ev[16];
    float lmax = -1e30f;
#pragma unroll
    for (int i = 0; i < 16; i++) {
        int s = t + i * 256;
        size_t idx = (size_t)b * SEQ + s;
        float e = 0.0f;
#pragma unroll
        for (int p = 0; p < 8; p++) e += g_e8[(size_t)p * MROWS + idx];
        ev[i] = e;
        if (s < len) lmax = fmaxf(lmax, e);
    }
    red[t] = lmax;
    __syncthreads();
    for (int o = 128; o > 0; o >>= 1) {
        if (t < o) red[t] = fmaxf(red[t], red[t + o]);
        __syncthreads();
    }
    float m = red[0];
    __syncthreads();

    float lsum = 0.0f;
#pragma unroll
    for (int i = 0; i < 16; i++) {
        int s = t + i * 256;
        float x = (s < len) ? __expf(ev[i] - m) : 0.0f;
        ev[i] = x;
        lsum += x;
    }
    red[t] = lsum;
    __syncthreads();
    for (int o = 128; o > 0; o >>= 1) {
        if (t < o) red[t] += red[t + o];
        __syncthreads();
    }
    float inv = 1.0f / red[0];

#pragma unroll
    for (int i = 0; i < 16; i++) {
        int s = t + i * 256;
        float a = ev[i] * inv;
        out[ATT_OFF + b * SEQ + s] = a;
        out[COV_OFF + b * SEQ + s] = cov[b * SEQ + s] + a;
    }
}

// ---------------------------------------------------------------------------
// 4) context[b] = sum_s attn[b,s] * enc[b,s,:]  — 64-row chunks, skip zeros
// ---------------------------------------------------------------------------
__global__ void context_kernel(const float* __restrict__ enc,
                               const float* __restrict__ out_attn,
                               float* __restrict__ ctx) {
    const int b = blockIdx.x;
    const int sc = blockIdx.y;          // 0..63, 64 rows each
    const int t = threadIdx.x;          // 256
    __shared__ float sa[64];
    if (t < 64) sa[t] = out_attn[b * SEQ + sc * 64 + t];
    int any = __syncthreads_or((t < 64) ? (sa[t] != 0.0f) : 0);
    if (!any) return;

    const float4* base =
        (const float4*)(enc + ((size_t)b * SEQ + sc * 64) * NDIM);
    float4 acc = make_float4(0.f, 0.f, 0.f, 0.f);
#pragma unroll 4
    for (int s = 0; s < 64; s++) {
        float a = sa[s];
        float4 x = base[s * 256 + t];
        acc.x += a * x.x;
        acc.y += a * x.y;
        acc.z += a * x.z;
        acc.w += a * x.w;
    }
    float* c = ctx + b * NDIM + t * 4;
    atomicAdd(c + 0, acc.x);
    atomicAdd(c + 1, acc.y);
    atomicAdd(c + 2, acc.z);
    atomicAdd(c + 3, acc.w);
}

// ---------------------------------------------------------------------------
// launch
// ---------------------------------------------------------------------------
extern "C" void kernel_launch(void* const* d_in, const int* in_sizes, int n_in,
                              void* d_out, int out_size) {
    const float* dec  = (const float*)d_in[0];  // [B,N]
    const float* enc  = (const float*)d_in[1];  // [B,S,N]
    const int*   lens = (const int*)  d_in[2];  // [B]
    const float* cov  = (const float*)d_in[3];  // [B,S]
    const float* Wh   = (const float*)d_in[4];  // [N,N]
    const float* bh   = (const float*)d_in[5];  // [N]
    const float* Ws   = (const float*)d_in[6];  // [N,N]
    const float* bs   = (const float*)d_in[7];  // [N]
    const float* wc   = (const float*)d_in[8];  // [N]
    const float* v    = (const float*)d_in[9];  // [N]
    float* out = (float*)d_out;

    cudaFuncSetAttribute(attn_gemm_kernel,
                         cudaFuncAttributeMaxDynamicSharedMemorySize, SMEM_BYTES);

    dec_feats_kernel<<<dim3(BATCH, 32), 256>>>(dec, Ws, bs, bh, lens);
    attn_gemm_kernel<<<GEMM_CTAS, 256, SMEM_BYTES>>>(enc, Wh, cov, wc, v, lens);
    softmax_kernel<<<BATCH, 256>>>(cov, lens, out);
    context_kernel<<<dim3(BATCH, SEQ / 64), 256>>>(enc, out + ATT_OFF, out + CTX_OFF);
}